// round 15
// baseline (speedup 1.0000x reference)
#include <cuda_runtime.h>
#include <cuda_fp16.h>
#include <math.h>
#include <stdint.h>

// Problem shape (fixed): B=4, N=10000, E=32, C=128, O=128
#define NN 10000
#define BN 40000        // B*N
#define CC 128
#define OO 128
#define EE 32
#define MT 64           // rows per GEMM tile
#define TILES 625       // 40000 / 64 exactly
#define GEMM_GRID 296   // 2 CTAs per SM

// ---------------------------------------------------------------------------
// Scratch (device globals — allocation-free rule)
// ---------------------------------------------------------------------------
__device__ float  g_A[(size_t)BN * OO];     // x @ (Wt - Wb) + bias   (fp32)
__device__ __half g_Ph[(size_t)BN * OO];    // x @ Wb                 (fp16)
__device__ int    g_idx64;                  // edge_index is int64?

__device__ __forceinline__ uint32_t smem_u32(const void* p) {
    uint32_t a;
    asm("{ .reg .u64 t; cvta.to.shared.u64 t, %1; cvt.u32.u64 %0, t; }" : "=r"(a) : "l"(p));
    return a;
}

#define LDSM_X4(r0, r1, r2, r3, a) \
    asm volatile("ldmatrix.sync.aligned.m8n8.x4.shared.b16 {%0,%1,%2,%3}, [%4];" \
                 : "=r"(r0), "=r"(r1), "=r"(r2), "=r"(r3) : "r"(a))

#define MMA16816(c, a0, a1, a2, a3, b0, b1) \
    asm volatile("mma.sync.aligned.m16n8k16.row.col.f32.f16.f16.f32 " \
                 "{%0,%1,%2,%3}, {%4,%5,%6,%7}, {%8,%9}, {%0,%1,%2,%3};" \
                 : "+f"((c)[0]), "+f"((c)[1]), "+f"((c)[2]), "+f"((c)[3]) \
                 : "r"(a0), "r"(a1), "r"(a2), "r"(a3), "r"(b0), "r"(b1))

// SMEM layout. Row stride 272B (272 mod 128 = 16 -> conflict-free ldmatrix).
#define ROWB   272
#define SM_A   0                          // 64 x 272 = 17408 (x fp16)
#define SM_B   17408                      // 256 x 272 = 69632 (w fp16)
#define SM_BIAS 87040                     // 128 floats
#define SMEM_SZ 87552                     // 2 CTAs/SM

// ---------------------------------------------------------------------------
// Persistent HMMA GEMM: [BN x 128] fp32 -> fp16 -> [BN x 256]
// One-time per CTA: convert W fp32 -> B^T fp16 directly into SMEM (fuses the
// old prep kernel); block 0 also detects edge_index dtype.
// Mainloop: register-prefetch next tile's x during epilogue to overlap DRAM
// latency with stores. cols 0:128 -> g_A fp32 (+bias), 128:256 -> g_Ph fp16.
// ---------------------------------------------------------------------------
__global__ __launch_bounds__(256, 2) void gemm_kernel(const float* __restrict__ x,
                                                      const float* __restrict__ W,
                                                      const float* __restrict__ bias,
                                                      const int* __restrict__ e32) {
    extern __shared__ char smem[];
    const uint32_t sb = smem_u32(smem);
    const int tid  = threadIdx.x;
    const int wid  = tid >> 5;
    const int lane = tid & 31;

    // ---- detect edge_index dtype (block 0, warp 0) ----
    if (blockIdx.x == 0 && wid == 0) {
        // int64 values are in (-1..9999): high word == sign-ext of low word.
        int ok = 1;
        for (int i = lane; i < 64; i += 32) {
            int lo = e32[2 * i];
            int hi = e32[2 * i + 1];
            int want = (lo < 0) ? -1 : 0;
            if (lo < -1 || lo >= NN || hi != want) ok = 0;
        }
        unsigned bl = __ballot_sync(0xffffffffu, ok);
        if (lane == 0) g_idx64 = (bl == 0xffffffffu) ? 1 : 0;
    }

    // ---- one-time: build B^T fp16 in SMEM from W fp32 (coalesced reads) ----
    // B^T[n][k] = n<128 ? Wt[k][n]-Wb[k][n] : Wb[k][n-128]
    {
        const int n = tid;                 // 0..255, warp-uniform branch below
        #pragma unroll 4
        for (int k = 0; k < CC; k++) {
            float v;
            if (n < OO) v = W[k * OO + n] - W[(k + CC) * OO + n];
            else        v = W[(k + CC) * OO + (n - OO)];
            __half h = __float2half_rn(v);
            *(uint16_t*)(smem + SM_B + n * ROWB + k * 2) =
                *reinterpret_cast<uint16_t*>(&h);
        }
        if (tid < OO) ((float*)(smem + SM_BIAS))[tid] = bias[tid];
    }

    const int wr = wid >> 2;               // warp row 0..1 -> rows wr*32
    const int wc = wid & 3;                // warp col 0..3 -> cols wc*64

    // ldmatrix base addresses (k-offset added per step)
    const uint32_t a_base = sb + SM_A + (wr * 32 + (lane & 15)) * ROWB + (lane >> 4) * 16;
    const uint32_t b_base = sb + SM_B +
        (wc * 64 + ((lane >> 4) & 1) * 8 + (lane & 7)) * ROWB + (((lane >> 3) & 1) * 16);

    // per-thread x-load geometry: f = i*256 + tid -> row = f>>5, c4 = f&31
    const int xrow = tid >> 5;             // base row advances by 8 per i
    const int xc4  = tid & 31;

    // ---- prologue: load tile0 + convert to SMEM ----
    int tile = blockIdx.x;
    float4 v[8];
    #pragma unroll
    for (int i = 0; i < 8; i++)
        v[i] = *(const float4*)(x + (size_t)(tile * MT + xrow + i * 8) * CC + xc4 * 4);

    while (true) {
        // convert prefetched regs -> SMEM A plane
        #pragma unroll
        for (int i = 0; i < 8; i++) {
            __half2 h01 = __floats2half2_rn(v[i].x, v[i].y);
            __half2 h23 = __floats2half2_rn(v[i].z, v[i].w);
            uint32_t hw0 = *reinterpret_cast<uint32_t*>(&h01);
            uint32_t hw1 = *reinterpret_cast<uint32_t*>(&h23);
            uint32_t off = (xrow + i * 8) * ROWB + xc4 * 8;
            asm volatile("st.shared.v2.b32 [%0], {%1, %2};"
                         :: "r"(sb + SM_A + off), "r"(hw0), "r"(hw1) : "memory");
        }
        __syncthreads();

        // ---- MMA: 8 k16-steps ----
        float acc[2][8][4];
        #pragma unroll
        for (int mi = 0; mi < 2; mi++)
            #pragma unroll
            for (int ni = 0; ni < 8; ni++)
                #pragma unroll
                for (int r = 0; r < 4; r++) acc[mi][ni][r] = 0.f;

        #pragma unroll
        for (int kk = 0; kk < 8; kk++) {
            const uint32_t kby = kk * 32;
            uint32_t a0[4], a1[4];
            LDSM_X4(a0[0], a0[1], a0[2], a0[3], a_base + kby);
            LDSM_X4(a1[0], a1[1], a1[2], a1[3], a_base + 16 * ROWB + kby);
            uint32_t b[4][4];
            #pragma unroll
            for (int j = 0; j < 4; j++)
                LDSM_X4(b[j][0], b[j][1], b[j][2], b[j][3], b_base + j * 16 * ROWB + kby);
            #pragma unroll
            for (int j = 0; j < 4; j++) {
                MMA16816(acc[0][2 * j + 0], a0[0], a0[1], a0[2], a0[3], b[j][0], b[j][1]);
                MMA16816(acc[0][2 * j + 1], a0[0], a0[1], a0[2], a0[3], b[j][2], b[j][3]);
                MMA16816(acc[1][2 * j + 0], a1[0], a1[1], a1[2], a1[3], b[j][0], b[j][1]);
                MMA16816(acc[1][2 * j + 1], a1[0], a1[1], a1[2], a1[3], b[j][2], b[j][3]);
            }
        }

        // ---- issue next tile's global loads (latency hidden by epilogue) ----
        const int next = tile + GEMM_GRID;
        const bool more = next < TILES;
        if (more) {
            #pragma unroll
            for (int i = 0; i < 8; i++)
                v[i] = *(const float4*)(x + (size_t)(next * MT + xrow + i * 8) * CC + xc4 * 4);
        }

        // ---- epilogue: cols<128 -> g_A fp32 (+bias); cols>=128 -> g_Ph fp16 ----
        {
            const int rowbase = tile * MT;
            const float* sbias = (const float*)(smem + SM_BIAS);
            const int g = lane >> 2;
            const int t = lane & 3;
            #pragma unroll
            for (int mi = 0; mi < 2; mi++) {
                #pragma unroll
                for (int half = 0; half < 2; half++) {
                    const int m = rowbase + wr * 32 + mi * 16 + g + half * 8;
                    #pragma unroll
                    for (int ni = 0; ni < 8; ni++) {
                        const int col = wc * 64 + ni * 8 + t * 2;
                        float c0 = acc[mi][ni][half * 2 + 0];
                        float c1 = acc[mi][ni][half * 2 + 1];
                        if (col < OO) {
                            float2 o = make_float2(c0 + sbias[col], c1 + sbias[col + 1]);
                            *(float2*)(g_A + (size_t)m * OO + col) = o;
                        } else {
                            __half2 h = __floats2half2_rn(c0, c1);
                            *(__half2*)(g_Ph + (size_t)m * OO + (col - OO)) = h;
                        }
                    }
                }
            }
        }
        __syncthreads();   // all warps done reading SM_A before overwrite
        if (!more) break;
        tile = next;
    }
}

// ---------------------------------------------------------------------------
// Gather-max + elu epilogue. One warp per node; fp16 P rows (256B/row),
// 16 half2 max accumulators, 8 LDG.64 in flight per iteration.
// ---------------------------------------------------------------------------
__device__ __forceinline__ float elu1(float v) {
    return v > 0.f ? v : expm1f(v);
}

__global__ __launch_bounds__(256) void gather_kernel(const void* __restrict__ eidx,
                                                     float* __restrict__ out) {
    const int gw = (blockIdx.x * 256 + threadIdx.x) >> 5;   // node row (b*N+n)
    const int lane = threadIdx.x & 31;
    if (gw >= BN) return;

    const int b = gw / NN;
    const int bbase = b * NN;

    const float4* __restrict__ A4 = (const float4*)g_A;
    const __half* __restrict__ Pb = g_Ph + (size_t)bbase * OO + lane * 4;

    int myidx;
    if (g_idx64) {
        myidx = (int)((const long long*)eidx)[(size_t)gw * EE + lane];
    } else {
        myidx = ((const int*)eidx)[(size_t)gw * EE + lane];
    }
    const unsigned vm = __ballot_sync(0xffffffffu, myidx >= 0);

    float4 a = A4[(size_t)gw * 32 + lane];   // prefetch early

    const __half2 ninf2 = __floats2half2_rn(-INFINITY, -INFINITY);
    __half2 ma[8], mb[8];
    #pragma unroll
    for (int s = 0; s < 8; s++) { ma[s] = ninf2; mb[s] = ninf2; }

    #pragma unroll
    for (int e = 0; e < EE; e += 8) {
        int j[8];
        #pragma unroll
        for (int s = 0; s < 8; s++)
            j[s] = __shfl_sync(0xffffffffu, myidx, e + s);
        #pragma unroll
        for (int s = 0; s < 8; s++) {
            if (j[s] >= 0) {
                uint2 r = *(const uint2*)(Pb + (size_t)j[s] * OO);
                ma[s] = __hmax2(ma[s], *reinterpret_cast<__half2*>(&r.x));
                mb[s] = __hmax2(mb[s], *reinterpret_cast<__half2*>(&r.y));
            }
        }
    }
    #pragma unroll
    for (int s = 0; s < 4; s++) { ma[s] = __hmax2(ma[s], ma[s + 4]); mb[s] = __hmax2(mb[s], mb[s + 4]); }
    ma[0] = __hmax2(__hmax2(ma[0], ma[1]), __hmax2(ma[2], ma[3]));
    mb[0] = __hmax2(__hmax2(mb[0], mb[1]), __hmax2(mb[2], mb[3]));

    float4 o;
    if (vm == 0u) {
        o = make_float4(-INFINITY, -INFINITY, -INFINITY, -INFINITY);
    } else {
        float2 fa = __half22float2(ma[0]);
        float2 fb = __half22float2(mb[0]);
        o.x = elu1(a.x + fa.x);
        o.y = elu1(a.y + fa.y);
        o.z = elu1(a.z + fb.x);
        o.w = elu1(a.w + fb.y);
    }
    reinterpret_cast<float4*>(out)[(size_t)gw * 32 + lane] = o;
}

// ---------------------------------------------------------------------------
// Launch (2 kernels total)
// ---------------------------------------------------------------------------
extern "C" void kernel_launch(void* const* d_in, const int* in_sizes, int n_in,
                              void* d_out, int out_size) {
    (void)in_sizes; (void)n_in; (void)out_size;
    const float* x    = (const float*)d_in[0];   // [B,N,C] fp32
    const void*  eidx = d_in[1];                 // [B,N,E] int64 or int32
    const float* W    = (const float*)d_in[2];   // [2C,O] fp32
    const float* bias = (const float*)d_in[3];   // [O] fp32
    float* out = (float*)d_out;                  // [B,N,O] fp32

    cudaFuncSetAttribute(gemm_kernel, cudaFuncAttributeMaxDynamicSharedMemorySize, SMEM_SZ);

    gemm_kernel<<<GEMM_GRID, 256, SMEM_SZ>>>(x, W, bias, (const int*)eidx);
    gather_kernel<<<BN / 8, 256>>>(eidx, out);
}